// round 7
// baseline (speedup 1.0000x reference)
#include <cuda_runtime.h>

// Fixed shapes
#define N_TOK 4096          // B*S
#define DIM   1024
#define NE    8
#define CAP   1280
#define NEC   ((size_t)N_TOK * NE * CAP)   // 41,943,040 floats
#define ECD   ((size_t)NE * CAP * DIM)     // 10,485,760 floats

#define LB      512                        // logits blocks (8 tokens each, warp/token)
#define ZB      4608                       // zero blocks
#define ZITER   20                         // float4 stores per zero thread
// total zeroed: 4608*256*20 float4 = 23,592,960 = (2*NEC + ECD)/4  (w+m+batches)

// Scratch (no allocations allowed -> device globals). All entries fully
// rewritten every replay -> deterministic under graph capture.
__device__ int      g_top[2][N_TOK];
__device__ float    g_prob[2][N_TOK];
__device__ unsigned g_tok_off[2][N_TOK];   // global slot e*CAP+r; 0xFFFFFFFF = dropped

// ---------------------------------------------------------------------------
// K1 (fused): blocks [0,LB) = router logits (warp per token);
//             blocks [LB,LB+ZB) = zero-fill w+m+batches (377 MB streaming).
// Logits compute hides entirely under the DRAM-bound zero traffic (R2: 7 TB/s).
// ---------------------------------------------------------------------------
__global__ void __launch_bounds__(256) k_main(const float* __restrict__ x,
                                              const float* __restrict__ w,
                                              float* __restrict__ out_zero_base,
                                              float* __restrict__ logits_out) {
    if (blockIdx.x >= LB) {
        float4* dst = (float4*)out_zero_base;
        unsigned t0 = (blockIdx.x - LB) * 256 + threadIdx.x;
        const unsigned stride = ZB * 256;
        const float4 z = make_float4(0.f, 0.f, 0.f, 0.f);
#pragma unroll
        for (int k = 0; k < ZITER; k++)
            dst[t0 + (size_t)k * stride] = z;
        return;
    }

    // ---- logits path ----
    __shared__ float4 ws4[NE * (DIM / 4)];   // 32 KB
    const int tid = threadIdx.x;
    const float4* w4 = (const float4*)w;
    for (int i = tid; i < NE * (DIM / 4); i += 256) ws4[i] = w4[i];
    __syncthreads();

    const int warp = tid >> 5, lane = tid & 31;
    const int n = blockIdx.x * 8 + warp;

    const float4* xr = (const float4*)(x + (size_t)n * DIM);
    float acc[NE];
#pragma unroll
    for (int e = 0; e < NE; e++) acc[e] = 0.f;

#pragma unroll
    for (int ii = 0; ii < (DIM / 4) / 32; ii++) {   // 8 iterations
        int i = lane + ii * 32;
        float4 xv = xr[i];
#pragma unroll
        for (int e = 0; e < NE; e++) {
            float4 wv = ws4[e * (DIM / 4) + i];
            acc[e] = fmaf(xv.x, wv.x, acc[e]);
            acc[e] = fmaf(xv.y, wv.y, acc[e]);
            acc[e] = fmaf(xv.z, wv.z, acc[e]);
            acc[e] = fmaf(xv.w, wv.w, acc[e]);
        }
    }
#pragma unroll
    for (int e = 0; e < NE; e++) {
#pragma unroll
        for (int o = 16; o > 0; o >>= 1)
            acc[e] += __shfl_down_sync(0xffffffffu, acc[e], o);
    }

    if (lane == 0) {
        // top-2, jax.lax.top_k tie-break (lowest index wins)
        int i0 = 0; float v0 = acc[0];
#pragma unroll
        for (int e = 1; e < NE; e++) if (acc[e] > v0) { v0 = acc[e]; i0 = e; }
        int i1 = -1; float v1 = -INFINITY;
#pragma unroll
        for (int e = 0; e < NE; e++)
            if (e != i0 && acc[e] > v1) { v1 = acc[e]; i1 = e; }
        float t   = expf(v1 - v0);          // <= 1
        float den = 1.f + t;
        g_top[0][n]  = i0;
        g_top[1][n]  = i1;
        g_prob[0][n] = 1.f / den;
        g_prob[1][n] = t / den;
#pragma unroll
        for (int e = 0; e < NE; e++) logits_out[(size_t)n * NE + e] = acc[e];
    }
}

// ---------------------------------------------------------------------------
// K2: ordered per-expert rank scan over 2*N assignments (k-major). 1 block,
// 1024 threads x 8 items. Scatters the ~16K nonzero weight/mask entries into
// the (already zeroed) output and records per-token slot offsets for K3.
// ---------------------------------------------------------------------------
__global__ void __launch_bounds__(1024) k_scan(float* __restrict__ out_w,
                                               float* __restrict__ out_m) {
    const int IPT = (2 * N_TOK) / 1024;   // 8
    const int tid  = threadIdx.x;
    const int lane = tid & 31, warp = tid >> 5;

    int cnt[NE];
#pragma unroll
    for (int e = 0; e < NE; e++) cnt[e] = 0;
    int ex[IPT];
    const int j0 = tid * IPT;
#pragma unroll
    for (int i = 0; i < IPT; i++) {
        int j = j0 + i;
        int k = (j >= N_TOK) ? 1 : 0;
        int n = j - k * N_TOK;
        int e = g_top[k][n];
        ex[i] = e;
        cnt[e]++;
    }

    int incl[NE];
#pragma unroll
    for (int e = 0; e < NE; e++) {
        int v = cnt[e];
#pragma unroll
        for (int o = 1; o < 32; o <<= 1) {
            int u = __shfl_up_sync(0xffffffffu, v, o);
            if (lane >= o) v += u;
        }
        incl[e] = v;
    }

    __shared__ int wtot[32][NE];
    __shared__ int wbase[32][NE];
    if (lane == 31) {
#pragma unroll
        for (int e = 0; e < NE; e++) wtot[warp][e] = incl[e];
    }
    __syncthreads();
    if (warp == 0) {
#pragma unroll
        for (int e = 0; e < NE; e++) {
            int v = wtot[lane][e];
            int iv = v;
#pragma unroll
            for (int o = 1; o < 32; o <<= 1) {
                int u = __shfl_up_sync(0xffffffffu, iv, o);
                if (lane >= o) iv += u;
            }
            wbase[lane][e] = iv - v;
        }
    }
    __syncthreads();

    int base[NE];
#pragma unroll
    for (int e = 0; e < NE; e++) base[e] = wbase[warp][e] + incl[e] - cnt[e];

#pragma unroll
    for (int i = 0; i < IPT; i++) {
        int j = j0 + i;
        int k = (j >= N_TOK) ? 1 : 0;
        int n = j - k * N_TOK;
        int e = ex[i];
        int r = base[e]++;
        float p = g_prob[k][n];
        unsigned off = 0xFFFFFFFFu;
        if (r < CAP && p > 0.f) {
            off = (unsigned)(e * CAP + r);
            size_t idx = (size_t)n * (NE * CAP) + off;
            out_w[idx] = p;
            out_m[idx] = 1.0f;
        }
        g_tok_off[k][n] = off;
    }
}

// ---------------------------------------------------------------------------
// K3: push expert batches. One block per token: read x row once (sequential),
// write it to the token's <=2 kept slots. Empty slots already zeroed by K1.
// ---------------------------------------------------------------------------
__global__ void __launch_bounds__(256) k_push(const float* __restrict__ x,
                                              float* __restrict__ out_b) {
    const int n = blockIdx.x;
    const unsigned off0 = g_tok_off[0][n];
    const unsigned off1 = g_tok_off[1][n];
    if (off0 == 0xFFFFFFFFu && off1 == 0xFFFFFFFFu) return;

    const int t = threadIdx.x;
    const float4 v = ((const float4*)(x + (size_t)n * DIM))[t];
    if (off0 != 0xFFFFFFFFu)
        ((float4*)(out_b + (size_t)off0 * DIM))[t] = v;
    if (off1 != 0xFFFFFFFFu)
        ((float4*)(out_b + (size_t)off1 * DIM))[t] = v;
}

// ---------------------------------------------------------------------------
extern "C" void kernel_launch(void* const* d_in, const int* in_sizes, int n_in,
                              void* d_out, int out_size) {
    const float* x = (const float*)d_in[0];
    const float* w = (const float*)d_in[1];
    if (in_sizes[0] == NE * DIM && in_sizes[1] == N_TOK * DIM) {
        const float* tmp = x; x = w; w = tmp;
    }

    float* out   = (float*)d_out;          // [N,E,cap] w | [N,E,cap] m | [E,cap,D] b | [B,S,E] l
    float* out_w = out;
    float* out_m = out + NEC;
    float* out_b = out + 2 * NEC;
    float* out_l = out + 2 * NEC + ECD;

    k_main<<<LB + ZB, 256>>>(x, w, out, out_l);   // zeroes w+m+b, writes logits
    k_scan<<<1, 1024>>>(out_w, out_m);
    k_push<<<N_TOK, 256>>>(x, out_b);
}

// round 8
// speedup vs baseline: 1.1622x; 1.1622x over previous
#include <cuda_runtime.h>

// Fixed shapes
#define N_TOK 4096          // B*S
#define DIM   1024
#define NE    8
#define CAP   1280
#define NEC   ((size_t)N_TOK * NE * CAP)   // 41,943,040 floats
#define ECD   ((size_t)NE * CAP * DIM)     // 10,485,760 floats

#define LB      512                        // logits blocks (8 tokens each, warp/token)
#define ZB      4096                       // zero blocks
#define ZITER   20                         // float4 stores per zero thread
// zeroed by K1: 4096*256*20 f4 = 20,971,520 = 2*NEC/4  (w+m only)

#define NSLOT   (NE * CAP)                 // 10240
#define SPB     4                          // slots per batch block
#define BB      (NSLOT / SPB)              // 2560 batch blocks

// Scratch (device globals; fully rewritten every replay -> graph-deterministic)
__device__ int g_top[2][N_TOK];
__device__ float g_prob[2][N_TOK];
__device__ int g_slot_token[NSLOT];

// ---------------------------------------------------------------------------
// K1 (fused): blocks [0,LB) = router logits (warp/token, w staged in smem);
//             blocks [LB,LB+ZB) = zero-fill weights+mask (335 MB streaming).
// ---------------------------------------------------------------------------
__global__ void __launch_bounds__(256) k_main(const float* __restrict__ x,
                                              const float* __restrict__ w,
                                              float* __restrict__ out_zero_base,
                                              float* __restrict__ logits_out) {
    if (blockIdx.x >= LB) {
        float4* dst = (float4*)out_zero_base;
        unsigned t0 = (blockIdx.x - LB) * 256 + threadIdx.x;
        const unsigned stride = ZB * 256;
        const float4 z = make_float4(0.f, 0.f, 0.f, 0.f);
#pragma unroll
        for (int k = 0; k < ZITER; k++)
            __stcs(&dst[t0 + (size_t)k * stride], z);
        return;
    }

    // ---- logits path ----
    __shared__ float4 ws4[NE * (DIM / 4)];   // 32 KB
    const int tid = threadIdx.x;
    const float4* w4 = (const float4*)w;
    for (int i = tid; i < NE * (DIM / 4); i += 256) ws4[i] = w4[i];
    __syncthreads();

    const int warp = tid >> 5, lane = tid & 31;
    const int n = blockIdx.x * 8 + warp;

    const float4* xr = (const float4*)(x + (size_t)n * DIM);
    float acc[NE];
#pragma unroll
    for (int e = 0; e < NE; e++) acc[e] = 0.f;

#pragma unroll
    for (int ii = 0; ii < (DIM / 4) / 32; ii++) {   // 8 iterations
        int i = lane + ii * 32;
        float4 xv = xr[i];
#pragma unroll
        for (int e = 0; e < NE; e++) {
            float4 wv = ws4[e * (DIM / 4) + i];
            acc[e] = fmaf(xv.x, wv.x, acc[e]);
            acc[e] = fmaf(xv.y, wv.y, acc[e]);
            acc[e] = fmaf(xv.z, wv.z, acc[e]);
            acc[e] = fmaf(xv.w, wv.w, acc[e]);
        }
    }
#pragma unroll
    for (int e = 0; e < NE; e++) {
#pragma unroll
        for (int o = 16; o > 0; o >>= 1)
            acc[e] += __shfl_down_sync(0xffffffffu, acc[e], o);
    }

    if (lane == 0) {
        // top-2, jax.lax.top_k tie-break (lowest index wins)
        int i0 = 0; float v0 = acc[0];
#pragma unroll
        for (int e = 1; e < NE; e++) if (acc[e] > v0) { v0 = acc[e]; i0 = e; }
        int i1 = -1; float v1 = -INFINITY;
#pragma unroll
        for (int e = 0; e < NE; e++)
            if (e != i0 && acc[e] > v1) { v1 = acc[e]; i1 = e; }
        float t   = expf(v1 - v0);          // <= 1
        float den = 1.f + t;
        g_top[0][n]  = i0;
        g_top[1][n]  = i1;
        g_prob[0][n] = 1.f / den;
        g_prob[1][n] = t / den;
#pragma unroll
        for (int e = 0; e < NE; e++) logits_out[(size_t)n * NE + e] = acc[e];
    }
}

// ---------------------------------------------------------------------------
// K2: ordered per-expert rank scan over 2*N assignments (k-major). 1 block,
// 1024 threads x 8 items. Scatters nonzero weight/mask entries into the
// zeroed output and fills the slot->token map for K3.
// ---------------------------------------------------------------------------
__global__ void __launch_bounds__(1024) k_scan(float* __restrict__ out_w,
                                               float* __restrict__ out_m) {
    const int IPT = (2 * N_TOK) / 1024;   // 8
    const int tid  = threadIdx.x;
    const int lane = tid & 31, warp = tid >> 5;

    for (int i = tid; i < NSLOT; i += 1024) g_slot_token[i] = -1;
    __syncthreads();

    int cnt[NE];
#pragma unroll
    for (int e = 0; e < NE; e++) cnt[e] = 0;
    int ex[IPT];
    const int j0 = tid * IPT;
#pragma unroll
    for (int i = 0; i < IPT; i++) {
        int j = j0 + i;
        int k = (j >= N_TOK) ? 1 : 0;
        int n = j - k * N_TOK;
        int e = g_top[k][n];
        ex[i] = e;
        cnt[e]++;
    }

    int incl[NE];
#pragma unroll
    for (int e = 0; e < NE; e++) {
        int v = cnt[e];
#pragma unroll
        for (int o = 1; o < 32; o <<= 1) {
            int u = __shfl_up_sync(0xffffffffu, v, o);
            if (lane >= o) v += u;
        }
        incl[e] = v;
    }

    __shared__ int wtot[32][NE];
    __shared__ int wbase[32][NE];
    if (lane == 31) {
#pragma unroll
        for (int e = 0; e < NE; e++) wtot[warp][e] = incl[e];
    }
    __syncthreads();
    if (warp == 0) {
#pragma unroll
        for (int e = 0; e < NE; e++) {
            int v = wtot[lane][e];
            int iv = v;
#pragma unroll
            for (int o = 1; o < 32; o <<= 1) {
                int u = __shfl_up_sync(0xffffffffu, iv, o);
                if (lane >= o) iv += u;
            }
            wbase[lane][e] = iv - v;
        }
    }
    __syncthreads();

    int base[NE];
#pragma unroll
    for (int e = 0; e < NE; e++) base[e] = wbase[warp][e] + incl[e] - cnt[e];

#pragma unroll
    for (int i = 0; i < IPT; i++) {
        int j = j0 + i;
        int k = (j >= N_TOK) ? 1 : 0;
        int n = j - k * N_TOK;
        int e = ex[i];
        int r = base[e]++;
        float p = g_prob[k][n];
        if (r < CAP && p > 0.f) {
            unsigned off = (unsigned)(e * CAP + r);
            size_t idx = (size_t)n * (NE * CAP) + off;
            out_w[idx] = p;
            out_m[idx] = 1.0f;
            g_slot_token[off] = n;
        }
    }
}

// ---------------------------------------------------------------------------
// K3: expert batches, MLP-optimized pull. Each block fills 4 slots: all 4
// x-row loads issue back-to-back (MLP_eff=4) before the 4 streaming stores.
// Empty slots write zeros. 2560 blocks x 256 threads.
// ---------------------------------------------------------------------------
__global__ void __launch_bounds__(256) k_batches(const float* __restrict__ x,
                                                 float* __restrict__ out_b) {
    const int bi = blockIdx.x;       // 0..BB-1
    const int t  = threadIdx.x;
    const int s0 = bi * SPB;

    int n0 = g_slot_token[s0 + 0];
    int n1 = g_slot_token[s0 + 1];
    int n2 = g_slot_token[s0 + 2];
    int n3 = g_slot_token[s0 + 3];

    const float4* xp = (const float4*)x;
    const float4 z = make_float4(0.f, 0.f, 0.f, 0.f);

    // issue all loads first (independent -> batched in SASS)
    float4 v0 = (n0 >= 0) ? __ldg(&xp[(size_t)n0 * (DIM / 4) + t]) : z;
    float4 v1 = (n1 >= 0) ? __ldg(&xp[(size_t)n1 * (DIM / 4) + t]) : z;
    float4 v2 = (n2 >= 0) ? __ldg(&xp[(size_t)n2 * (DIM / 4) + t]) : z;
    float4 v3 = (n3 >= 0) ? __ldg(&xp[(size_t)n3 * (DIM / 4) + t]) : z;

    float4* ob = (float4*)out_b;
    __stcs(&ob[(size_t)(s0 + 0) * (DIM / 4) + t], v0);
    __stcs(&ob[(size_t)(s0 + 1) * (DIM / 4) + t], v1);
    __stcs(&ob[(size_t)(s0 + 2) * (DIM / 4) + t], v2);
    __stcs(&ob[(size_t)(s0 + 3) * (DIM / 4) + t], v3);
}

// ---------------------------------------------------------------------------
extern "C" void kernel_launch(void* const* d_in, const int* in_sizes, int n_in,
                              void* d_out, int out_size) {
    const float* x = (const float*)d_in[0];
    const float* w = (const float*)d_in[1];
    if (in_sizes[0] == NE * DIM && in_sizes[1] == N_TOK * DIM) {
        const float* tmp = x; x = w; w = tmp;
    }

    float* out   = (float*)d_out;          // [N,E,cap] w | [N,E,cap] m | [E,cap,D] b | [B,S,E] l
    float* out_w = out;
    float* out_m = out + NEC;
    float* out_b = out + 2 * NEC;
    float* out_l = out + 2 * NEC + ECD;

    k_main<<<LB + ZB, 256>>>(x, w, out, out_l);   // zero w+m, logits hidden under it
    k_scan<<<1, 1024>>>(out_w, out_m);
    k_batches<<<BB, 256>>>(x, out_b);
}